// round 2
// baseline (speedup 1.0000x reference)
#include <cuda_runtime.h>

#define TT 512
#define LL 62
#define KK 64
#define SMALLV (-1000.0f)

__global__ void init_out_kernel(float* out) { out[0] = 0.0f; }

__global__ __launch_bounds__(KK) void crf_forward_kernel(
    const float* __restrict__ pred,      // [B, T, L]
    const int*   __restrict__ ref,       // [B, T]
    const int*   __restrict__ seq_len,   // [B]
    const float* __restrict__ trans,     // [K, K]
    float* __restrict__ out)             // scalar
{
    const int b    = blockIdx.x;
    const int j    = threadIdx.x;        // state column owned by this thread
    const int lane = j & 31;
    const int wid  = j >> 5;

    __shared__ __align__(16) float a_sh[KK];
    __shared__ float red[2];
    __shared__ float red2[2];

    const float* predb = pred + (size_t)b * TT * LL;
    const int*   refb  = ref  + (size_t)b * TT;
    const int    sl    = seq_len[b];

    // E[k][j] = exp(trans[k][j]) held in registers (column j per thread).
    // Rows 62,63 are -10000 -> exp underflows to exactly 0 (correct: those
    // states never feed forward).
    float Ecol[KK];
    #pragma unroll
    for (int k = 0; k < KK; ++k) Ecol[k] = __expf(trans[k * KK + j]);

    // alpha init = b_s: labels -1000, start(62)=0, end(63)=-1000
    float alpha = (j == LL) ? 0.0f : SMALLV;

    // ---- forward scan: steps 1..sl, then boundary step sl+1 ----
    for (int s = 1; s <= sl + 1; ++s) {
        // observation for this step (hoisted LDG overlaps the reductions)
        float obs;
        if (s <= sl) {
            obs = (j < LL) ? predb[(s - 1) * LL + j] : SMALLV;
        } else {
            // boundary row: labels = base-1000 (base = pred row if sl<T else 0),
            // start = -1000, end = 0
            if (j < LL)
                obs = ((sl < TT) ? predb[sl * LL + j] : 0.0f) + SMALLV;
            else
                obs = (j == LL) ? SMALLV : 0.0f;
        }

        // m = max over LABEL alphas only (start/end rows of E are 0)
        float v = (j < LL) ? alpha : -3.0e38f;
        #pragma unroll
        for (int off = 16; off; off >>= 1)
            v = fmaxf(v, __shfl_xor_sync(0xffffffffu, v, off));
        if (lane == 0) red[wid] = v;
        __syncthreads();
        const float m = fmaxf(red[0], red[1]);

        // a[k] = exp(alpha_k - m) for labels, 0 for start/end (avoids inf*0)
        a_sh[j] = (j < LL) ? __expf(alpha - m) : 0.0f;
        __syncthreads();

        // acc = sum_k a[k] * E[k][j]   (E in regs, a broadcast via LDS.128)
        float acc0 = 0.f, acc1 = 0.f, acc2 = 0.f, acc3 = 0.f;
        #pragma unroll
        for (int k = 0; k < KK; k += 4) {
            const float4 av = *reinterpret_cast<const float4*>(&a_sh[k]);
            acc0 = fmaf(av.x, Ecol[k + 0], acc0);
            acc1 = fmaf(av.y, Ecol[k + 1], acc1);
            acc2 = fmaf(av.z, Ecol[k + 2], acc2);
            acc3 = fmaf(av.w, Ecol[k + 3], acc3);
        }
        const float acc = (acc0 + acc1) + (acc2 + acc3);

        alpha = obs + m + __logf(acc);
    }

    // ---- all-paths score: logsumexp over all 64 final alphas ----
    float v = alpha;
    #pragma unroll
    for (int off = 16; off; off >>= 1)
        v = fmaxf(v, __shfl_xor_sync(0xffffffffu, v, off));
    if (lane == 0) red[wid] = v;
    __syncthreads();
    const float M = fmaxf(red[0], red[1]);

    float e = __expf(alpha - M);
    #pragma unroll
    for (int off = 16; off; off >>= 1)
        e += __shfl_xor_sync(0xffffffffu, e, off);
    if (lane == 0) red2[wid] = e;
    __syncthreads();
    const float all_paths = M + __logf(red2[0] + red2[1]);

    // ---- gold (real) score ----
    float gold = 0.0f;
    for (int t = j; t < sl; t += KK)
        gold += predb[t * LL + refb[t]];
    for (int t = j; t <= sl; t += KK) {
        const int from = (t == 0)  ? LL       : refb[t - 1];
        const int to   = (t == sl) ? (LL + 1) : refb[t];
        gold += trans[from * KK + to];
    }
    #pragma unroll
    for (int off = 16; off; off >>= 1)
        gold += __shfl_xor_sync(0xffffffffu, gold, off);
    if (lane == 0) red[wid] = gold;   // red's last read was before prior barrier
    __syncthreads();
    const float gold_total = red[0] + red[1];

    if (j == 0)
        atomicAdd(out, all_paths - gold_total);
}

extern "C" void kernel_launch(void* const* d_in, const int* in_sizes, int n_in,
                              void* d_out, int out_size)
{
    const float* pred    = (const float*)d_in[0];
    const int*   ref     = (const int*)d_in[1];
    const int*   seq_len = (const int*)d_in[2];
    const float* trans   = (const float*)d_in[3];
    float*       out     = (float*)d_out;

    const int B = in_sizes[2];   // 1024

    init_out_kernel<<<1, 1>>>(out);
    crf_forward_kernel<<<B, KK>>>(pred, ref, seq_len, trans, out);
}

// round 3
// speedup vs baseline: 1.7594x; 1.7594x over previous
#include <cuda_runtime.h>

#define TT 512
#define LL 62
#define KK 64
#define GG 8

__global__ void init_out_kernel(float* out) { out[0] = 0.0f; }

__device__ __forceinline__ unsigned long long pack2f(float lo, float hi) {
    unsigned long long r;
    asm("mov.b64 %0, {%1, %2};" : "=l"(r) : "f"(lo), "f"(hi));
    return r;
}
__device__ __forceinline__ void unpack2f(unsigned long long v, float& lo, float& hi) {
    asm("mov.b64 {%0, %1}, %2;" : "=f"(lo), "=f"(hi) : "l"(v));
}
__device__ __forceinline__ unsigned long long ffma2(unsigned long long a,
                                                    unsigned long long b,
                                                    unsigned long long c) {
    unsigned long long d;
    asm("fma.rn.f32x2 %0, %1, %2, %3;" : "=l"(d) : "l"(a), "l"(b), "l"(c));
    return d;
}
__device__ __forceinline__ unsigned long long fadd2(unsigned long long a,
                                                    unsigned long long b) {
    unsigned long long d;
    asm("add.rn.f32x2 %0, %1, %2;" : "=l"(d) : "l"(a), "l"(b));
    return d;
}

// dot_j = sum_{k=0}^{63} ubuf[k] * E[k][j]   (E column j packed per thread;
// rows 62,63 of E are exactly 0, and ubuf[62..63] are 0)
__device__ __forceinline__ float dot64(const float* __restrict__ ubuf,
                                       const unsigned long long* __restrict__ Epk) {
    const ulonglong2* up = reinterpret_cast<const ulonglong2*>(ubuf);
    unsigned long long a0 = 0ull, a1 = 0ull, a2 = 0ull, a3 = 0ull;
    #pragma unroll
    for (int q = 0; q < 16; q += 2) {
        ulonglong2 v0 = up[q];
        ulonglong2 v1 = up[q + 1];
        a0 = ffma2(v0.x, Epk[2 * q + 0], a0);
        a1 = ffma2(v0.y, Epk[2 * q + 1], a1);
        a2 = ffma2(v1.x, Epk[2 * q + 2], a2);
        a3 = ffma2(v1.y, Epk[2 * q + 3], a3);
    }
    unsigned long long aa = fadd2(fadd2(a0, a1), fadd2(a2, a3));
    float lo, hi;
    unpack2f(aa, lo, hi);
    return lo + hi;
}

__global__ __launch_bounds__(KK) void crf_forward_kernel(
    const float* __restrict__ pred,      // [B, T, L]
    const int*   __restrict__ ref,       // [B, T]
    const int*   __restrict__ seq_len,   // [B]
    const float* __restrict__ trans,     // [K, K]
    float* __restrict__ out)             // scalar
{
    const int b    = blockIdx.x;
    const int j    = threadIdx.x;
    const int lane = j & 31;
    const int wid  = j >> 5;

    __shared__ __align__(16) float u_sh[2][KK];
    __shared__ float red[2];
    __shared__ float red2[2];

    const float* predb = pred + (size_t)b * TT * LL;
    const int*   refb  = ref  + (size_t)b * TT;
    const int    sl    = seq_len[b];

    // E column j, packed as f32x2 pairs (rows 2p, 2p+1). exp(-10000) -> 0.
    unsigned long long Epk[KK / 2];
    #pragma unroll
    for (int p = 0; p < KK / 2; ++p) {
        float e0 = __expf(trans[(2 * p + 0) * KK + j]);
        float e1 = __expf(trans[(2 * p + 1) * KK + j]);
        Epk[p] = pack2f(e0, e1);
    }

    // alpha init b_s = labels -1000, start 0, end -1000. Start's outgoing E row
    // is 0, so it never propagates: scan over labels only, carried as
    // u_j = exp(alpha_j - c), c = -1000 -> u = 1 for labels, 0 otherwise.
    float u = (j < LL) ? 1.0f : 0.0f;
    float c = -1000.0f;
    u_sh[0][j] = u;
    int cur = 0;

    // obs register pipeline: one 8-step group ahead
    float obsA[GG], obsB[GG];
    #pragma unroll
    for (int i = 0; i < GG; ++i)
        obsA[i] = (j < LL) ? __ldg(&predb[i * LL + j]) : -1000.0f;

    int s = 1;
    while (s + GG <= sl + 1) {               // full group: steps s .. s+7 (all <= sl)
        #pragma unroll
        for (int i = 0; i < GG; ++i) {       // prefetch steps s+8 .. s+15
            const int row = s + GG - 1 + i;
            obsB[i] = (j < LL && row < TT) ? __ldg(&predb[row * LL + j]) : -1000.0f;
        }
        #pragma unroll
        for (int i = 0; i < GG; ++i) {
            const float eobs = __expf(obsA[i]);
            __syncthreads();
            float un = eobs * dot64(u_sh[cur], Epk);
            if ((i & 3) == 3) {              // renorm every 4 steps by u[0]
                const float u0 = u_sh[cur][0];
                c += __logf(u0);
                un = __fdividef(un, u0);
            }
            u = un;
            u_sh[cur ^ 1][j] = u;
            cur ^= 1;
        }
        #pragma unroll
        for (int i = 0; i < GG; ++i) obsA[i] = obsB[i];
        s += GG;
    }

    const int rem = sl + 1 - s;              // 0..7 remaining steps s..sl
    #pragma unroll
    for (int i = 0; i < GG - 1; ++i) {
        if (i >= rem) break;
        const float eobs = __expf(obsA[i]);
        __syncthreads();
        float un = eobs * dot64(u_sh[cur], Epk);
        if ((i & 3) == 3) {
            const float u0 = u_sh[cur][0];
            c += __logf(u0);
            un = __fdividef(un, u0);
        }
        u = un;
        u_sh[cur ^ 1][j] = u;
        cur ^= 1;
    }
    __syncthreads();

    // ---- boundary step (step sl+1) in log domain, all 64 columns ----
    const float dB = dot64(u_sh[cur], Epk);
    float obs_b;
    if (j < LL)
        obs_b = ((sl < TT) ? predb[sl * LL + j] : 0.0f) - 1000.0f;
    else
        obs_b = (j == LL) ? -1000.0f : 0.0f;
    const float alpha_fin = obs_b + c + __logf(dB);

    // ---- all-paths score: logsumexp over 64 final alphas ----
    float v = alpha_fin;
    #pragma unroll
    for (int off = 16; off; off >>= 1)
        v = fmaxf(v, __shfl_xor_sync(0xffffffffu, v, off));
    if (lane == 0) red[wid] = v;
    __syncthreads();
    const float M = fmaxf(red[0], red[1]);

    float e = __expf(alpha_fin - M);
    #pragma unroll
    for (int off = 16; off; off >>= 1)
        e += __shfl_xor_sync(0xffffffffu, e, off);
    if (lane == 0) red2[wid] = e;
    __syncthreads();
    const float all_paths = M + __logf(red2[0] + red2[1]);

    // ---- gold (real) score ----
    float gold = 0.0f;
    for (int t = j; t < sl; t += KK)
        gold += predb[t * LL + refb[t]];
    for (int t = j; t <= sl; t += KK) {
        const int from = (t == 0)  ? LL       : refb[t - 1];
        const int to   = (t == sl) ? (LL + 1) : refb[t];
        gold += trans[from * KK + to];
    }
    #pragma unroll
    for (int off = 16; off; off >>= 1)
        gold += __shfl_xor_sync(0xffffffffu, gold, off);
    if (lane == 0) red[wid] = gold;
    __syncthreads();
    const float gold_total = red[0] + red[1];

    if (j == 0)
        atomicAdd(out, all_paths - gold_total);
}

extern "C" void kernel_launch(void* const* d_in, const int* in_sizes, int n_in,
                              void* d_out, int out_size)
{
    const float* pred    = (const float*)d_in[0];
    const int*   ref     = (const int*)d_in[1];
    const int*   seq_len = (const int*)d_in[2];
    const float* trans   = (const float*)d_in[3];
    float*       out     = (float*)d_out;

    const int B = in_sizes[2];   // 1024

    init_out_kernel<<<1, 1>>>(out);
    crf_forward_kernel<<<B, KK>>>(pred, ref, seq_len, trans, out);
}

// round 4
// speedup vs baseline: 2.2134x; 1.2580x over previous
#include <cuda_runtime.h>
#include <cuda_bf16.h>

#define TT 512
#define LL 62
#define KK 64
#define GG 8

__global__ void init_out_kernel(float* out) { out[0] = 0.0f; }

__device__ __forceinline__ __nv_bfloat162 u32_as_bf2(unsigned int v) {
    __nv_bfloat162 r;
    *reinterpret_cast<unsigned int*>(&r) = v;
    return r;
}

// dot_j = sum_{k=0}^{63} u[k] * E[k][j], u in shared as bf16, E column j in
// bf16x2 register pairs (rows 2p, 2p+1). Rows 62,63 of E are exactly 0.
__device__ __forceinline__ float dot64h(const __nv_bfloat16* __restrict__ ubuf,
                                        const __nv_bfloat162* __restrict__ Epk) {
    const uint4* up = reinterpret_cast<const uint4*>(ubuf);
    __nv_bfloat162 z; *reinterpret_cast<unsigned int*>(&z) = 0u;
    __nv_bfloat162 a0 = z, a1 = z, a2 = z, a3 = z;
    #pragma unroll
    for (int q = 0; q < 8; ++q) {
        uint4 v = up[q];                       // 8 bf16 = 4 pairs
        a0 = __hfma2(u32_as_bf2(v.x), Epk[4 * q + 0], a0);
        a1 = __hfma2(u32_as_bf2(v.y), Epk[4 * q + 1], a1);
        a2 = __hfma2(u32_as_bf2(v.z), Epk[4 * q + 2], a2);
        a3 = __hfma2(u32_as_bf2(v.w), Epk[4 * q + 3], a3);
    }
    __nv_bfloat162 s = __hadd2(__hadd2(a0, a1), __hadd2(a2, a3));
    float2 f = __bfloat1622float2(s);
    return f.x + f.y;
}

__global__ __launch_bounds__(KK) void crf_forward_kernel(
    const float* __restrict__ pred,      // [B, T, L]
    const int*   __restrict__ ref,       // [B, T]
    const int*   __restrict__ seq_len,   // [B]
    const float* __restrict__ trans,     // [K, K]
    float* __restrict__ out)             // scalar
{
    const int b    = blockIdx.x;
    const int j    = threadIdx.x;
    const int lane = j & 31;
    const int wid  = j >> 5;

    __shared__ __align__(16) __nv_bfloat16 u_sh[2][KK];
    __shared__ float red[2];
    __shared__ float red2[2];

    const float* predb = pred + (size_t)b * TT * LL;
    const int*   refb  = ref  + (size_t)b * TT;
    const int    sl    = seq_len[b];

    // E column j as bf16x2 pairs. exp(-10000) -> 0 exactly (rows 62, 63).
    __nv_bfloat162 Epk[KK / 2];
    #pragma unroll
    for (int p = 0; p < KK / 2; ++p) {
        float e0 = __expf(trans[(2 * p + 0) * KK + j]);
        float e1 = __expf(trans[(2 * p + 1) * KK + j]);
        Epk[p] = __floats2bfloat162_rn(e0, e1);
    }

    // u_j = exp(alpha_j - c); init: labels 1.0 (alpha=-1000), start/end 0.
    // Start's outgoing E row is 0, so dropping its unit mass is exact; the
    // initial distribution over labels is what b_s encodes at c=-1000.
    float c = -1000.0f;
    u_sh[0][j] = __float2bfloat16((j < LL) ? 1.0f : 0.0f);
    int cur = 0;

    // eobs register pipeline, one 8-step group ahead (exp done at prefetch)
    float eobsA[GG], eobsB[GG];
    #pragma unroll
    for (int i = 0; i < GG; ++i)
        eobsA[i] = (j < LL) ? __expf(__ldg(&predb[i * LL + j])) : 0.0f;

    int s = 1;
    while (s + GG <= sl + 1) {               // steps s..s+7, all emission steps
        #pragma unroll
        for (int i = 0; i < GG; ++i) {       // prefetch steps s+8 .. s+15
            const int row = s + GG - 1 + i;
            eobsB[i] = (j < LL && row < TT) ? __expf(__ldg(&predb[row * LL + j]))
                                            : 0.0f;
        }
        #pragma unroll
        for (int i = 0; i < GG; ++i) {
            __syncthreads();
            float un = eobsA[i] * dot64h(u_sh[cur], Epk);
            if ((i & 3) == 3) {              // renorm every 4 steps by u[0]
                const float u0 = __bfloat162float(u_sh[cur][0]);
                c += __logf(u0);
                un = __fdividef(un, u0);
            }
            u_sh[cur ^ 1][j] = __float2bfloat16(un);
            cur ^= 1;
        }
        #pragma unroll
        for (int i = 0; i < GG; ++i) eobsA[i] = eobsB[i];
        s += GG;
    }

    const int rem = sl + 1 - s;              // 0..7 remaining emission steps
    #pragma unroll
    for (int i = 0; i < GG - 1; ++i) {
        if (i >= rem) break;
        __syncthreads();
        float un = eobsA[i] * dot64h(u_sh[cur], Epk);
        if ((i & 3) == 3) {
            const float u0 = __bfloat162float(u_sh[cur][0]);
            c += __logf(u0);
            un = __fdividef(un, u0);
        }
        u_sh[cur ^ 1][j] = __float2bfloat16(un);
        cur ^= 1;
    }
    __syncthreads();

    // ---- boundary step (step sl+1) in log domain, all 64 columns ----
    const float dB = dot64h(u_sh[cur], Epk);
    float obs_b;
    if (j < LL)
        obs_b = ((sl < TT) ? predb[sl * LL + j] : 0.0f) - 1000.0f;
    else
        obs_b = (j == LL) ? -1000.0f : 0.0f;
    const float alpha_fin = obs_b + c + __logf(dB);

    // ---- all-paths score: logsumexp over 64 final alphas (fp32) ----
    float v = alpha_fin;
    #pragma unroll
    for (int off = 16; off; off >>= 1)
        v = fmaxf(v, __shfl_xor_sync(0xffffffffu, v, off));
    if (lane == 0) red[wid] = v;
    __syncthreads();
    const float M = fmaxf(red[0], red[1]);

    float e = __expf(alpha_fin - M);
    #pragma unroll
    for (int off = 16; off; off >>= 1)
        e += __shfl_xor_sync(0xffffffffu, e, off);
    if (lane == 0) red2[wid] = e;
    __syncthreads();
    const float all_paths = M + __logf(red2[0] + red2[1]);

    // ---- gold (real) score (exact fp32) ----
    float gold = 0.0f;
    for (int t = j; t < sl; t += KK)
        gold += predb[t * LL + refb[t]];
    for (int t = j; t <= sl; t += KK) {
        const int from = (t == 0)  ? LL       : refb[t - 1];
        const int to   = (t == sl) ? (LL + 1) : refb[t];
        gold += trans[from * KK + to];
    }
    #pragma unroll
    for (int off = 16; off; off >>= 1)
        gold += __shfl_xor_sync(0xffffffffu, gold, off);
    if (lane == 0) red[wid] = gold;
    __syncthreads();
    const float gold_total = red[0] + red[1];

    if (j == 0)
        atomicAdd(out, all_paths - gold_total);
}

extern "C" void kernel_launch(void* const* d_in, const int* in_sizes, int n_in,
                              void* d_out, int out_size)
{
    const float* pred    = (const float*)d_in[0];
    const int*   ref     = (const int*)d_in[1];
    const int*   seq_len = (const int*)d_in[2];
    const float* trans   = (const float*)d_in[3];
    float*       out     = (float*)d_out;

    const int B = in_sizes[2];   // 1024

    init_out_kernel<<<1, 1>>>(out);
    crf_forward_kernel<<<B, KK>>>(pred, ref, seq_len, trans, out);
}